// round 1
// baseline (speedup 1.0000x reference)
#include <cuda_runtime.h>
#include <cuda_bf16.h>
#include <stdint.h>

// ---------------------------------------------------------------------------
// TypeLoss: focal loss over (n_pairs, 4) logits with sparse one-hot targets
// built by scattering 200K relations.
//
// Phases:
//   1) zero 4-bit-per-pair mask array
//   2) scatter relations -> atomicOr class bits
//   3) main: per-pair focal loss, block partial sums (deterministic)
//   4) final: fixed-order sum of partials in double, mean, write d_out
// ---------------------------------------------------------------------------

#define MAX_PAIRS   9000000          // >= 3000*3000 - 3000 = 8,997,000
#define MASK_WORDS  (MAX_PAIRS / 4)  // 1 byte per pair, packed in uint32
#define MAIN_BLOCKS 1184             // 8 blocks * 148 SMs
#define MAIN_THREADS 256

__device__ unsigned int g_mask[MASK_WORDS];
__device__ float        g_partials[MAIN_BLOCKS];

// ---- Phase 1: zero the mask region actually used ----
__global__ void zero_mask_kernel(int nwords) {
    int idx    = blockIdx.x * blockDim.x + threadIdx.x;
    int stride = gridDim.x * blockDim.x;
    uint4* p4  = reinterpret_cast<uint4*>(g_mask);
    int n4 = nwords >> 2;
    uint4 z = make_uint4(0u, 0u, 0u, 0u);
    for (int i = idx; i < n4; i += stride) p4[i] = z;
    for (int i = (n4 << 2) + idx; i < nwords; i += stride) g_mask[i] = 0u;
}

// ---- Phase 2: scatter relations into the mask ----
__device__ __forceinline__ int pred_to_type(int pred) {
    // _TABLE: support {1,14..26}->1, proximity {2..7}->2, comparative {8..13}->3, else 0
    if (pred == 1 || (pred >= 14 && pred <= 26)) return 1;
    if (pred >= 2 && pred <= 7)  return 2;
    if (pred >= 8 && pred <= 13) return 3;
    return 0;
}

__global__ void scatter_kernel(const int* __restrict__ rel, int n_rel, int insnum) {
    int r = blockIdx.x * blockDim.x + threadIdx.x;
    if (r >= n_rel) return;
    int i    = rel[3 * r + 0];
    int j    = rel[3 * r + 1];
    int pred = rel[3 * r + 2];
    if (i == j) return;                    // flat -> n_pairs, mode='drop'
    // defensive bounds (mode='drop' semantics)
    if (i < 0 || j < 0 || i >= insnum || j >= insnum) return;
    int t = pred_to_type(pred < 0 ? 0 : (pred > 63 ? 63 : pred));
    int flat = i * (insnum - 1) + j - (i < j ? 1 : 0);
    unsigned word  = (unsigned)flat >> 2;
    unsigned shift = (((unsigned)flat & 3u) << 3) + (unsigned)t;
    atomicOr(&g_mask[word], 1u << shift);
}

// ---- Phase 3: focal loss + deterministic per-block partial sums ----
__global__ __launch_bounds__(MAIN_THREADS) void loss_kernel(
    const float4* __restrict__ logits,
    const float*  __restrict__ pred_w,
    int n_pairs)
{
    const unsigned char* __restrict__ mask = reinterpret_cast<const unsigned char*>(g_mask);
    const float w0 = pred_w[0], w1 = pred_w[1], w2 = pred_w[2], w3 = pred_w[3];

    float acc = 0.0f;
    int idx    = blockIdx.x * blockDim.x + threadIdx.x;
    int stride = gridDim.x * blockDim.x;

    for (int i = idx; i < n_pairs; i += stride) {
        float4 l = __ldcs(&logits[i]);          // streaming: dataset > L2
        unsigned m = mask[i];
        if (m == 0u) m = 1u;                    // empty row -> class 0

        float mx = fmaxf(fmaxf(l.x, l.y), fmaxf(l.z, l.w));
        float e0 = __expf(l.x - mx);
        float e1 = __expf(l.y - mx);
        float e2 = __expf(l.z - mx);
        float e3 = __expf(l.w - mx);
        float S  = (e0 + e1) + (e2 + e3);

        float num = 0.0f, a = 0.0f;
        if (m & 1u) { num += e0; a += w0; }
        if (m & 2u) { num += e1; a += w1; }
        if (m & 4u) { num += e2; a += w2; }
        if (m & 8u) { num += e3; a += w3; }

        float p  = __fdividef(num, S);
        float om = 1.0f - p;
        acc += a * om * om * (-__logf(p));
    }

    // block tree reduction (deterministic)
    __shared__ float sdata[MAIN_THREADS];
    sdata[threadIdx.x] = acc;
    __syncthreads();
    #pragma unroll
    for (int s = MAIN_THREADS / 2; s > 0; s >>= 1) {
        if (threadIdx.x < s) sdata[threadIdx.x] += sdata[threadIdx.x + s];
        __syncthreads();
    }
    if (threadIdx.x == 0) g_partials[blockIdx.x] = sdata[0];
}

// ---- Phase 4: fixed-order final reduction, mean, write output ----
__global__ void finalize_kernel(float* __restrict__ out, int n_pairs) {
    __shared__ double sdata[256];
    double acc = 0.0;
    for (int i = threadIdx.x; i < MAIN_BLOCKS; i += 256)
        acc += (double)g_partials[i];
    sdata[threadIdx.x] = acc;
    __syncthreads();
    for (int s = 128; s > 0; s >>= 1) {
        if (threadIdx.x < s) sdata[threadIdx.x] += sdata[threadIdx.x + s];
        __syncthreads();
    }
    if (threadIdx.x == 0)
        out[0] = (float)(sdata[0] / (double)n_pairs);
}

// ---------------------------------------------------------------------------
extern "C" void kernel_launch(void* const* d_in, const int* in_sizes, int n_in,
                              void* d_out, int out_size) {
    const float* type_output = (const float*)d_in[0];   // (n_pairs, 4) f32
    // d_in[1] = obj_gt (insnum,) int32 — only its size is needed
    const int*   rel_gt      = (const int*)d_in[2];     // (n_rel, 3) int32
    const float* pred_w      = (const float*)d_in[3];   // (4,) f32

    int insnum  = in_sizes[1];
    int n_rel   = in_sizes[2] / 3;
    int n_pairs = insnum * insnum - insnum;
    int nwords  = (n_pairs + 3) / 4;

    zero_mask_kernel<<<512, 256>>>(nwords);
    scatter_kernel<<<(n_rel + 255) / 256, 256>>>(rel_gt, n_rel, insnum);
    loss_kernel<<<MAIN_BLOCKS, MAIN_THREADS>>>(
        (const float4*)type_output, pred_w, n_pairs);
    finalize_kernel<<<1, 256>>>((float*)d_out, n_pairs);
}